// round 3
// baseline (speedup 1.0000x reference)
#include <cuda_runtime.h>

#define SX 512
#define NG (SX * SX)          // 262144 grid cells
#define SCAN_B 1024           // cells per scan block
#define SCAN_NB (NG / SCAN_B) // 256 scan blocks

// ---- scratch (device globals; no allocation allowed) ----
__device__ unsigned char g_occ[NG];
__device__ unsigned char g_core[NG];
__device__ int g_parent[NG];
__device__ int g_rootlab[NG];   // read-only-derived root label per core cell
__device__ int g_rootflag[NG];
__device__ int g_dense[NG];
__device__ int g_raw[NG];
__device__ int g_voxd[NG];
__device__ int g_counts[NG];
__device__ int g_final[NG];
__device__ int g_bsum[SCAN_NB];
__device__ int g_maxinst;

// voxelization: must match jnp: floor((p - (-51.2f)) / 0.2f) in fp32
__device__ __forceinline__ int voxel_of(float px, float py) {
    int cx = (int)floorf((px - (-51.2f)) / 0.2f);
    int cy = (int)floorf((py - (-51.2f)) / 0.2f);
    cx = min(max(cx, 0), SX - 1);
    cy = min(max(cy, 0), SX - 1);
    return cy * SX + cx;
}

// Used ONLY inside k_union (races quiesce at kernel boundary; final roots are
// component minima regardless of schedule).
__device__ int find_root(int x) {
    while (true) {
        int p = g_parent[x];
        if (p == x) return x;
        int gp = g_parent[p];
        if (gp != p) g_parent[x] = gp;   // path halving (benign inside k_union)
        x = p;
    }
}

// Pure-read root chase: used AFTER k_union, when g_parent is static.
__device__ int find_root_ro(int x) {
    int p = g_parent[x];
    while (p != x) { x = p; p = g_parent[x]; }
    return x;
}

__device__ void unite(int a, int b) {
    int ra = find_root(a);
    int rb = find_root(b);
    while (ra != rb) {
        if (ra < rb) { int t = ra; ra = rb; rb = t; }
        // hook larger root under smaller -> final roots are component minima
        int prev = atomicCAS(&g_parent[ra], ra, rb);
        if (prev == ra) return;
        ra = find_root(prev);
        rb = find_root(rb);
    }
}

// K0: reset all state (deterministic across graph replays)
__global__ void k_clear() {
    int i = blockIdx.x * blockDim.x + threadIdx.x;
    if (i >= NG) return;
    g_occ[i] = 0;
    g_core[i] = 0;
    g_parent[i] = i;
    g_rootflag[i] = 0;
    g_counts[i] = 0;
    g_final[i] = -1;
    if (i == 0) g_maxinst = 0;
}

// K1: occupancy from points
__global__ void k_occ(const float* __restrict__ pts, int N) {
    int i = blockIdx.x * blockDim.x + threadIdx.x;
    if (i >= N) return;
    int v = voxel_of(pts[i * 5 + 1], pts[i * 5 + 2]);
    g_occ[v] = 1;
}

// K2: core = occupied && (>=5 occupied in 3x3 incl self)   [eps=1.5 => 8-neighborhood]
__global__ void k_core() {
    int i = blockIdx.x * blockDim.x + threadIdx.x;
    if (i >= NG) return;
    if (!g_occ[i]) return;
    int x = i & (SX - 1), y = i >> 9;
    int cnt = 0;
    #pragma unroll
    for (int dy = -1; dy <= 1; dy++) {
        int ny = y + dy;
        if (ny < 0 || ny >= SX) continue;
        #pragma unroll
        for (int dx = -1; dx <= 1; dx++) {
            int nx = x + dx;
            if (nx < 0 || nx >= SX) continue;
            cnt += g_occ[ny * SX + nx];
        }
    }
    g_core[i] = (cnt >= 5);
}

// K3: union-find over core-core 8-edges (each undirected edge processed once)
__global__ void k_union() {
    int i = blockIdx.x * blockDim.x + threadIdx.x;
    if (i >= NG) return;
    if (!g_core[i]) return;
    int x = i & (SX - 1), y = i >> 9;
    const int ddx[4] = {-1, -1, 0, 1};
    const int ddy[4] = {0, -1, -1, -1};
    #pragma unroll
    for (int k = 0; k < 4; k++) {
        int nx = x + ddx[k], ny = y + ddy[k];
        if (nx < 0 || nx >= SX || ny < 0 || ny >= SX) continue;
        int n = ny * SX + nx;
        if (g_core[n]) unite(i, n);
    }
}

// K4: extract roots READ-ONLY (g_parent static now => fully deterministic)
__global__ void k_flatten() {
    int i = blockIdx.x * blockDim.x + threadIdx.x;
    if (i >= NG) return;
    if (!g_core[i]) return;
    int r = find_root_ro(i);
    g_rootlab[i] = r;
    g_rootflag[i] = (r == i);
}

// K5: raw label per occupied voxel (core: own root; border: min root over core nbrs; else -1)
__global__ void k_raw() {
    int i = blockIdx.x * blockDim.x + threadIdx.x;
    if (i >= NG) return;
    if (!g_occ[i]) return;
    int raw;
    if (g_core[i]) {
        raw = g_rootlab[i];
    } else {
        raw = -1;
        int best = 0x7fffffff;
        int x = i & (SX - 1), y = i >> 9;
        #pragma unroll
        for (int dy = -1; dy <= 1; dy++) {
            int ny = y + dy;
            if (ny < 0 || ny >= SX) continue;
            #pragma unroll
            for (int dx = -1; dx <= 1; dx++) {
                int nx = x + dx;
                if (nx < 0 || nx >= SX) continue;
                int n = ny * SX + nx;
                if (g_core[n]) best = min(best, g_rootlab[n]);
            }
        }
        if (best != 0x7fffffff) raw = best;
    }
    g_raw[i] = raw;
}

// K6a: per-block root counts
__global__ void k_scan_a() {
    __shared__ int sh[SCAN_B];
    int t = threadIdx.x;
    sh[t] = g_rootflag[blockIdx.x * SCAN_B + t];
    __syncthreads();
    for (int s = SCAN_B / 2; s > 0; s >>= 1) {
        if (t < s) sh[t] += sh[t + s];
        __syncthreads();
    }
    if (t == 0) g_bsum[blockIdx.x] = sh[0];
}

// K6b: exclusive scan of the 256 block sums (single block)
__global__ void k_scan_b() {
    __shared__ int sh[SCAN_NB];
    int t = threadIdx.x;
    int orig = g_bsum[t];
    sh[t] = orig;
    __syncthreads();
    for (int d = 1; d < SCAN_NB; d <<= 1) {
        int v = (t >= d) ? sh[t - d] : 0;
        __syncthreads();
        sh[t] += v;
        __syncthreads();
    }
    g_bsum[t] = sh[t] - orig;  // exclusive
}

// K6c: dense id for each root cell = global exclusive rank in row-major order
__global__ void k_scan_c() {
    int i = blockIdx.x * SCAN_B + threadIdx.x;
    int flag = g_rootflag[i];
    int lane = threadIdx.x & 31, wid = threadIdx.x >> 5;
    unsigned mask = 0xffffffffu;
    int x = flag;
    #pragma unroll
    for (int d = 1; d < 32; d <<= 1) {
        int t = __shfl_up_sync(mask, x, d);
        if (lane >= d) x += t;
    }
    __shared__ int wsum[32], woff[32];
    if (lane == 31) wsum[wid] = x;
    __syncthreads();
    if (wid == 0) {
        int v = wsum[lane];
        int s = v;
        #pragma unroll
        for (int d = 1; d < 32; d <<= 1) {
            int t = __shfl_up_sync(mask, s, d);
            if (lane >= d) s += t;
        }
        woff[lane] = s - v;
    }
    __syncthreads();
    if (flag) g_dense[i] = g_bsum[blockIdx.x] + woff[wid] + (x - flag);
}

// K7: per-voxel dense label + voxel counts per cluster
__global__ void k_count() {
    int i = blockIdx.x * blockDim.x + threadIdx.x;
    if (i >= NG) return;
    if (!g_occ[i]) return;
    int r = g_raw[i];
    if (r >= 0) {
        int d = g_dense[r];
        g_voxd[i] = d;
        atomicAdd(&g_counts[d], 1);
    } else {
        g_voxd[i] = -1;
    }
}

// K8: drop clusters with < 20 voxels; track max instance id
__global__ void k_final() {
    int i = blockIdx.x * blockDim.x + threadIdx.x;
    if (i >= NG) return;
    if (!g_occ[i]) return;
    int d = g_voxd[i];
    int f = (d >= 0 && g_counts[d] >= 20) ? d : -1;
    g_final[i] = f;
    atomicMax(&g_maxinst, f + 1);
}

// K9: scatter labels back to points; append max_num_inst
__global__ void k_out(const float* __restrict__ pts, int N, float* __restrict__ out, int out_size) {
    int i = blockIdx.x * blockDim.x + threadIdx.x;
    if (i < N) {
        int v = voxel_of(pts[i * 5 + 1], pts[i * 5 + 2]);
        out[i] = (float)g_final[v];
    }
    if (i == 0 && out_size > N) out[N] = (float)g_maxinst;
}

extern "C" void kernel_launch(void* const* d_in, const int* in_sizes, int n_in,
                              void* d_out, int out_size) {
    const float* pts = (const float*)d_in[0];
    int N = in_sizes[0] / 5;
    float* out = (float*)d_out;

    const int GB = NG / 256;
    k_clear<<<GB, 256>>>();
    k_occ<<<(N + 255) / 256, 256>>>(pts, N);
    k_core<<<GB, 256>>>();
    k_union<<<GB, 256>>>();
    k_flatten<<<GB, 256>>>();
    k_raw<<<GB, 256>>>();
    k_scan_a<<<SCAN_NB, SCAN_B>>>();
    k_scan_b<<<1, SCAN_NB>>>();
    k_scan_c<<<SCAN_NB, SCAN_B>>>();
    k_count<<<GB, 256>>>();
    k_final<<<GB, 256>>>();
    k_out<<<(N + 255) / 256, 256>>>(pts, N, out, out_size);
}